// round 8
// baseline (speedup 1.0000x reference)
#include <cuda_runtime.h>
#include <cuda_bf16.h>
#include <math.h>
#include <stdint.h>

#define BATCH 8192
#define KDIM  1024
#define HDIM  1024
#define FH    4096

// Gate pre-activations (fp32) + bf16 hi/lo split operands.
__device__ float g_ig[(size_t)BATCH * FH];
__device__ float g_hg[(size_t)BATCH * FH];
__device__ __nv_bfloat16 g_Ahi[(size_t)BATCH * KDIM], g_Alo[(size_t)BATCH * KDIM];
__device__ __nv_bfloat16 g_Hhi[(size_t)BATCH * KDIM], g_Hlo[(size_t)BATCH * KDIM];
__device__ __nv_bfloat16 g_Wihi[(size_t)FH * KDIM],  g_Wilo[(size_t)FH * KDIM];
__device__ __nv_bfloat16 g_Whhi[(size_t)FH * KDIM],  g_Whlo[(size_t)FH * KDIM];

// ---------------------------------------------------------------------------
// Split fp32 -> bf16 hi + bf16 lo. blockIdx.y selects tensor.
// ---------------------------------------------------------------------------
__device__ __forceinline__ uint32_t pack_bf16(float a, float b) {
    __nv_bfloat16 ha = __float2bfloat16(a), hb = __float2bfloat16(b);
    return ((uint32_t)__bfloat16_as_ushort(hb) << 16) | __bfloat16_as_ushort(ha);
}

__global__ void __launch_bounds__(256)
split_kernel(const float* __restrict__ s0, const float* __restrict__ s1,
             const float* __restrict__ s2, const float* __restrict__ s3,
             __nv_bfloat16* __restrict__ h0, __nv_bfloat16* __restrict__ l0,
             __nv_bfloat16* __restrict__ h1, __nv_bfloat16* __restrict__ l1,
             __nv_bfloat16* __restrict__ h2, __nv_bfloat16* __restrict__ l2,
             __nv_bfloat16* __restrict__ h3, __nv_bfloat16* __restrict__ l3)
{
    const float* src; __nv_bfloat16 *hi, *lo; int n4;
    switch (blockIdx.y) {
        case 0: src = s0; hi = h0; lo = l0; n4 = (BATCH * KDIM) / 4; break;
        case 1: src = s1; hi = h1; lo = l1; n4 = (BATCH * KDIM) / 4; break;
        case 2: src = s2; hi = h2; lo = l2; n4 = (FH * KDIM) / 4; break;
        default: src = s3; hi = h3; lo = l3; n4 = (FH * KDIM) / 4; break;
    }
    int i = blockIdx.x * blockDim.x + threadIdx.x;
    int stride = gridDim.x * blockDim.x;
    for (; i < n4; i += stride) {
        float4 v = ((const float4*)src)[i];
        float hx_ = __bfloat162float(__float2bfloat16(v.x));
        float hy_ = __bfloat162float(__float2bfloat16(v.y));
        float hz_ = __bfloat162float(__float2bfloat16(v.z));
        float hw_ = __bfloat162float(__float2bfloat16(v.w));
        uint2 ph, pl;
        ph.x = pack_bf16(v.x, v.y);
        ph.y = pack_bf16(v.z, v.w);
        pl.x = pack_bf16(v.x - hx_, v.y - hy_);
        pl.y = pack_bf16(v.z - hz_, v.w - hw_);
        ((uint2*)hi)[i] = ph;
        ((uint2*)lo)[i] = pl;
    }
}

// ---------------------------------------------------------------------------
// GEMM: out[m,n] = sum_k A[m,k] * W[n,k]  via bf16x3 split mma.sync m16n8k16.
// CTA tile 128x256, K-chunk 32, 3 stages, 8 warps (2x4), warp tile 64x64.
// ---------------------------------------------------------------------------
#define BM 128
#define BN 256
#define KC 32
#define NCHUNK (KDIM / KC)                 // 32
#define ROWB  80                           // bytes per smem row (32 bf16 = 64B + 16 pad)
#define AT_B  (BM * ROWB)                  // 10240 per component
#define BT_B  (BN * ROWB)                  // 20480 per component
#define OFF_ALO  AT_B                      // 10240
#define OFF_BHI  (2 * AT_B)                // 20480
#define OFF_BLO  (2 * AT_B + BT_B)         // 40960
#define STAGE_BYTES (2 * AT_B + 2 * BT_B)  // 61440
#define SMEM_TOTAL (3 * STAGE_BYTES)       // 184320
#define NTHREADS 256

__device__ __forceinline__ uint32_t smem_u32(const void* p) {
    uint32_t a;
    asm("{ .reg .u64 t; cvta.to.shared.u64 t, %1; cvt.u32.u64 %0, t; }" : "=r"(a) : "l"(p));
    return a;
}

__device__ __forceinline__ void cp16(uint32_t saddr, const void* g) {
    asm volatile("cp.async.cg.shared.global [%0], [%1], 16;" :: "r"(saddr), "l"(g));
}
#define CP_COMMIT() asm volatile("cp.async.commit_group;" ::: "memory")
#define CP_WAIT_1() asm volatile("cp.async.wait_group 1;" ::: "memory")

__device__ __forceinline__ void ldsm4(uint32_t& r0, uint32_t& r1, uint32_t& r2, uint32_t& r3,
                                      uint32_t addr) {
    asm volatile("ldmatrix.sync.aligned.m8n8.x4.shared.b16 {%0,%1,%2,%3}, [%4];"
                 : "=r"(r0), "=r"(r1), "=r"(r2), "=r"(r3) : "r"(addr));
}

__device__ __forceinline__ void mma_bf16(float c[4], const uint32_t a[4], const uint32_t b[2]) {
    asm volatile(
        "mma.sync.aligned.m16n8k16.row.col.f32.bf16.bf16.f32 "
        "{%0,%1,%2,%3}, {%4,%5,%6,%7}, {%8,%9}, {%0,%1,%2,%3};"
        : "+f"(c[0]), "+f"(c[1]), "+f"(c[2]), "+f"(c[3])
        : "r"(a[0]), "r"(a[1]), "r"(a[2]), "r"(a[3]),
          "r"(b[0]), "r"(b[1]));
}

__global__ void __launch_bounds__(NTHREADS, 1)
gemm_bf16x3_kernel(const __nv_bfloat16* __restrict__ Ahi, const __nv_bfloat16* __restrict__ Alo,
                   const __nv_bfloat16* __restrict__ Whi, const __nv_bfloat16* __restrict__ Wlo,
                   float* __restrict__ out)
{
    extern __shared__ char smem[];
    const uint32_t sbase = smem_u32(smem);

    const int tid  = threadIdx.x;
    const int wid  = tid >> 5;
    const int lane = tid & 31;
    const int wm   = wid >> 2;     // 0..1 -> 64-row slab
    const int wn   = wid & 3;      // 0..3 -> 64-col slab
    const int m0   = blockIdx.y * BM;
    const int n0   = blockIdx.x * BN;

    // Loader: rows of 64B data = 4x16B chunks. id -> (row = id>>2, c = id&3)
    auto load_stage = [&](int st, int c) {
        const uint32_t sb = sbase + st * STAGE_BYTES;
        const int kt = c * KC;
        #pragma unroll
        for (int i = 0; i < 2; i++) {               // A hi: 512 chunks
            int id = tid + i * 256;
            int row = id >> 2, ch = id & 3;
            cp16(sb + row * ROWB + ch * 16,
                 &Ahi[(size_t)(m0 + row) * KDIM + kt + ch * 8]);
        }
        #pragma unroll
        for (int i = 0; i < 2; i++) {               // A lo
            int id = tid + i * 256;
            int row = id >> 2, ch = id & 3;
            cp16(sb + OFF_ALO + row * ROWB + ch * 16,
                 &Alo[(size_t)(m0 + row) * KDIM + kt + ch * 8]);
        }
        #pragma unroll
        for (int i = 0; i < 4; i++) {               // B hi: 1024 chunks
            int id = tid + i * 256;
            int row = id >> 2, ch = id & 3;
            cp16(sb + OFF_BHI + row * ROWB + ch * 16,
                 &Whi[(size_t)(n0 + row) * KDIM + kt + ch * 8]);
        }
        #pragma unroll
        for (int i = 0; i < 4; i++) {               // B lo
            int id = tid + i * 256;
            int row = id >> 2, ch = id & 3;
            cp16(sb + OFF_BLO + row * ROWB + ch * 16,
                 &Wlo[(size_t)(n0 + row) * KDIM + kt + ch * 8]);
        }
    };

    // ldmatrix lane addressing: lanes 0-15 -> rows, lanes 16-31 -> rows at k+8
    const int lrow = lane & 15;
    const int lkof = (lane >> 4) * 16;    // bytes
    uint32_t offA[4], offB[4];
    #pragma unroll
    for (int mt = 0; mt < 4; mt++)
        offA[mt] = (wm * 64 + mt * 16 + lrow) * ROWB + lkof;
    #pragma unroll
    for (int p = 0; p < 4; p++)
        offB[p] = (uint32_t)OFF_BHI + (wn * 64 + p * 16 + lrow) * ROWB + lkof;

    float acc[4][8][4];
    #pragma unroll
    for (int mt = 0; mt < 4; mt++)
        #pragma unroll
        for (int nt = 0; nt < 8; nt++)
            #pragma unroll
            for (int r = 0; r < 4; r++)
                acc[mt][nt][r] = 0.f;

    load_stage(0, 0); CP_COMMIT();
    load_stage(1, 1); CP_COMMIT();

    int st = 0;
    for (int c = 0; c < NCHUNK; c++) {
        CP_WAIT_1();
        __syncthreads();

        int st2 = st + 2; if (st2 >= 3) st2 -= 3;
        if (c + 2 < NCHUNK) load_stage(st2, c + 2);
        CP_COMMIT();

        const uint32_t sb = sbase + st * STAGE_BYTES;

        #pragma unroll
        for (int ks = 0; ks < 2; ks++) {           // two k16 steps per chunk
            const uint32_t kb = ks * 32;           // 16 bf16 = 32 bytes

            // hi fragments
            uint32_t ah[4][4], bh[8][2];
            #pragma unroll
            for (int mt = 0; mt < 4; mt++)
                ldsm4(ah[mt][0], ah[mt][1], ah[mt][2], ah[mt][3], sb + offA[mt] + kb);
            #pragma unroll
            for (int p = 0; p < 4; p++)
                ldsm4(bh[2*p][0], bh[2*p+1][0], bh[2*p][1], bh[2*p+1][1],
                      sb + offB[p] + kb);
            // pass 1: hi*hi
            #pragma unroll
            for (int mt = 0; mt < 4; mt++)
                #pragma unroll
                for (int nt = 0; nt < 8; nt++)
                    mma_bf16(acc[mt][nt], ah[mt], bh[nt]);

            // lo A fragments; pass 2: lo*hi
            uint32_t al[4][4];
            #pragma unroll
            for (int mt = 0; mt < 4; mt++)
                ldsm4(al[mt][0], al[mt][1], al[mt][2], al[mt][3],
                      sb + OFF_ALO + offA[mt] + kb);
            #pragma unroll
            for (int mt = 0; mt < 4; mt++)
                #pragma unroll
                for (int nt = 0; nt < 8; nt++)
                    mma_bf16(acc[mt][nt], al[mt], bh[nt]);

            // lo B fragments; pass 3: hi*lo
            uint32_t bl[8][2];
            #pragma unroll
            for (int p = 0; p < 4; p++)
                ldsm4(bl[2*p][0], bl[2*p+1][0], bl[2*p][1], bl[2*p+1][1],
                      sb + (OFF_BLO - OFF_BHI) + offB[p] + kb);
            #pragma unroll
            for (int mt = 0; mt < 4; mt++)
                #pragma unroll
                for (int nt = 0; nt < 8; nt++)
                    mma_bf16(acc[mt][nt], ah[mt], bl[nt]);
        }

        if (++st >= 3) st -= 3;
    }

    // epilogue
    #pragma unroll
    for (int mt = 0; mt < 4; mt++) {
        int row0 = m0 + wm * 64 + mt * 16 + (lane >> 2);
        #pragma unroll
        for (int nt = 0; nt < 8; nt++) {
            int col0 = n0 + wn * 64 + nt * 8 + 2 * (lane & 3);
            *(float2*)&out[(size_t)row0 * FH + col0] =
                make_float2(acc[mt][nt][0], acc[mt][nt][1]);
            *(float2*)&out[(size_t)(row0 + 8) * FH + col0] =
                make_float2(acc[mt][nt][2], acc[mt][nt][3]);
        }
    }
}

// ---------------------------------------------------------------------------
// Fused LayerNorm + LSTM gates + cell LayerNorm (register-resident, R7).
// ---------------------------------------------------------------------------
__device__ __forceinline__ float sigmoidf_(float x) {
    return 1.f / (1.f + expf(-x));
}

__device__ __forceinline__ float2 block_sum2(float2 v, float2* sh) {
    #pragma unroll
    for (int o = 16; o > 0; o >>= 1) {
        v.x += __shfl_down_sync(0xffffffffu, v.x, o);
        v.y += __shfl_down_sync(0xffffffffu, v.y, o);
    }
    int lane = threadIdx.x & 31, w = threadIdx.x >> 5;
    if (lane == 0) sh[w] = v;
    __syncthreads();
    if (w == 0) {
        float2 t = (lane < 8) ? sh[lane] : make_float2(0.f, 0.f);
        #pragma unroll
        for (int o = 4; o > 0; o >>= 1) {
            t.x += __shfl_down_sync(0xffffffffu, t.x, o);
            t.y += __shfl_down_sync(0xffffffffu, t.y, o);
        }
        if (lane == 0) sh[0] = t;
    }
    __syncthreads();
    return sh[0];
}

__global__ void __launch_bounds__(256)
fuse_kernel(const float* __restrict__ cx,
            const float* __restrict__ ln_i_w, const float* __restrict__ ln_i_b,
            const float* __restrict__ ln_h_w, const float* __restrict__ ln_h_b,
            const float* __restrict__ ln_c_w, const float* __restrict__ ln_c_b,
            float* __restrict__ out)
{
    const int b   = blockIdx.x;
    const int tid = threadIdx.x;
    const float4* ig4 = (const float4*)(g_ig + (size_t)b * FH);
    const float4* hg4 = (const float4*)(g_hg + (size_t)b * FH);

    __shared__ float2 red_i[8], red_h[8], red_c[8];

    float4 vi[4], vh[4];
    float2 si = make_float2(0.f, 0.f), sh_ = make_float2(0.f, 0.f);
    #pragma unroll
    for (int p = 0; p < 4; p++) {
        int j = tid + p * 256;
        float4 a = ig4[j], c = hg4[j];
        vi[p] = a; vh[p] = c;
        si.x += a.x + a.y + a.z + a.w;
        si.y += a.x*a.x + a.y*a.y + a.z*a.z + a.w*a.w;
        sh_.x += c.x + c.y + c.z + c.w;
        sh_.y += c.x*c.x + c.y*c.y + c.z*c.z + c.w*c.w;
    }
    float2 ri = block_sum2(si, red_i);
    float2 rh = block_sum2(sh_, red_h);

    const float inv_fh = 1.f / (float)FH;
    float mu_i = ri.x * inv_fh;
    float rs_i = rsqrtf(ri.y * inv_fh - mu_i * mu_i + 1e-5f);
    float mu_h = rh.x * inv_fh;
    float rs_h = rsqrtf(rh.y * inv_fh - mu_h * mu_h + 1e-5f);

    float4 g[4];
    #pragma unroll
    for (int p = 0; p < 4; p++) {
        int j = tid + p * 256;
        float4 wi = ((const float4*)ln_i_w)[j], bi = ((const float4*)ln_i_b)[j];
        float4 wh = ((const float4*)ln_h_w)[j], bh = ((const float4*)ln_h_b)[j];
        float4 a = vi[p], c = vh[p];
        g[p].x = (a.x - mu_i) * rs_i * wi.x + bi.x + (c.x - mu_h) * rs_h * wh.x + bh.x;
        g[p].y = (a.y - mu_i) * rs_i * wi.y + bi.y + (c.y - mu_h) * rs_h * wh.y + bh.y;
        g[p].z = (a.z - mu_i) * rs_i * wi.z + bi.z + (c.z - mu_h) * rs_h * wh.z + bh.z;
        g[p].w = (a.w - mu_i) * rs_i * wi.w + bi.w + (c.w - mu_h) * rs_h * wh.w + bh.w;
    }

    float4 c4 = ((const float4*)cx)[b * 256 + tid];

    float4 cv;
    cv.x = sigmoidf_(g[1].x) * c4.x + sigmoidf_(g[0].x) * tanhf(g[2].x);
    cv.y = sigmoidf_(g[1].y) * c4.y + sigmoidf_(g[0].y) * tanhf(g[2].y);
    cv.z = sigmoidf_(g[1].z) * c4.z + sigmoidf_(g[0].z) * tanhf(g[2].z);
    cv.w = sigmoidf_(g[1].w) * c4.w + sigmoidf_(g[0].w) * tanhf(g[2].w);

    float2 sc = make_float2(cv.x + cv.y + cv.z + cv.w,
                            cv.x*cv.x + cv.y*cv.y + cv.z*cv.z + cv.w*cv.w);
    float2 rc = block_sum2(sc, red_c);
    const float inv_h = 1.f / (float)HDIM;
    float mu_c = rc.x * inv_h;
    float rs_c = rsqrtf(rc.y * inv_h - mu_c * mu_c + 1e-5f);

    float4 wc = ((const float4*)ln_c_w)[tid], bc = ((const float4*)ln_c_b)[tid];
    float4 cy, hy;
    cy.x = (cv.x - mu_c) * rs_c * wc.x + bc.x;  hy.x = sigmoidf_(g[3].x) * tanhf(cy.x);
    cy.y = (cv.y - mu_c) * rs_c * wc.y + bc.y;  hy.y = sigmoidf_(g[3].y) * tanhf(cy.y);
    cy.z = (cv.z - mu_c) * rs_c * wc.z + bc.z;  hy.z = sigmoidf_(g[3].z) * tanhf(cy.z);
    cy.w = (cv.w - mu_c) * rs_c * wc.w + bc.w;  hy.w = sigmoidf_(g[3].w) * tanhf(cy.w);

    ((float4*)out)[(size_t)b * 256 + tid] = hy;
    ((float4*)out)[(size_t)BATCH * 256 + (size_t)b * 256 + tid] = cy;
}

// ---------------------------------------------------------------------------
extern "C" void kernel_launch(void* const* d_in, const int* in_sizes, int n_in,
                              void* d_out, int out_size)
{
    const float* input  = (const float*)d_in[0];
    const float* hx     = (const float*)d_in[1];
    const float* cx     = (const float*)d_in[2];
    const float* wih    = (const float*)d_in[3];
    const float* whh    = (const float*)d_in[4];
    const float* ln_i_w = (const float*)d_in[5];
    const float* ln_i_b = (const float*)d_in[6];
    const float* ln_h_w = (const float*)d_in[7];
    const float* ln_h_b = (const float*)d_in[8];
    const float* ln_c_w = (const float*)d_in[9];
    const float* ln_c_b = (const float*)d_in[10];
    float* out = (float*)d_out;

    cudaFuncSetAttribute(gemm_bf16x3_kernel,
                         cudaFuncAttributeMaxDynamicSharedMemorySize, SMEM_TOTAL);

    __nv_bfloat16 *dAhi, *dAlo, *dHhi, *dHlo, *dWihi, *dWilo, *dWhhi, *dWhlo;
    float *dIG, *dHG;
    cudaGetSymbolAddress((void**)&dAhi,  g_Ahi);
    cudaGetSymbolAddress((void**)&dAlo,  g_Alo);
    cudaGetSymbolAddress((void**)&dHhi,  g_Hhi);
    cudaGetSymbolAddress((void**)&dHlo,  g_Hlo);
    cudaGetSymbolAddress((void**)&dWihi, g_Wihi);
    cudaGetSymbolAddress((void**)&dWilo, g_Wilo);
    cudaGetSymbolAddress((void**)&dWhhi, g_Whhi);
    cudaGetSymbolAddress((void**)&dWhlo, g_Whlo);
    cudaGetSymbolAddress((void**)&dIG, g_ig);
    cudaGetSymbolAddress((void**)&dHG, g_hg);

    split_kernel<<<dim3(160, 4), 256>>>(input, hx, wih, whh,
                                        dAhi, dAlo, dHhi, dHlo,
                                        dWihi, dWilo, dWhhi, dWhlo);

    dim3 grid(FH / BN, BATCH / BM);
    gemm_bf16x3_kernel<<<grid, NTHREADS, SMEM_TOTAL>>>(dAhi, dAlo, dWihi, dWilo, dIG);
    gemm_bf16x3_kernel<<<grid, NTHREADS, SMEM_TOTAL>>>(dHhi, dHlo, dWhhi, dWhlo, dHG);
    fuse_kernel<<<BATCH, 256>>>(cx, ln_i_w, ln_i_b, ln_h_w, ln_h_b, ln_c_w, ln_c_b, out);
}

// round 9
// speedup vs baseline: 1.6082x; 1.6082x over previous
#include <cuda_runtime.h>
#include <math.h>
#include <stdint.h>

#define BATCH 8192
#define KDIM  1024
#define HDIM  1024
#define FH    4096

// Scratch: raw gate pre-activations + tf32-prerounded operand copies.
__device__ float g_ig[(size_t)BATCH * FH];
__device__ float g_hg[(size_t)BATCH * FH];
__device__ float g_A [(size_t)BATCH * KDIM];
__device__ float g_H [(size_t)BATCH * KDIM];
__device__ float g_Wi[(size_t)FH * KDIM];
__device__ float g_Wh[(size_t)FH * KDIM];

// ---------------------------------------------------------------------------
// tf32 pre-rounding (RNA), all 4 tensors in one launch (blockIdx.y selects).
// ---------------------------------------------------------------------------
__device__ __forceinline__ float to_tf32(float x) {
    uint32_t u;
    asm("cvt.rna.tf32.f32 %0, %1;" : "=r"(u) : "f"(x));
    return __uint_as_float(u);
}

__global__ void __launch_bounds__(256)
round_all_kernel(const float* __restrict__ s0, const float* __restrict__ s1,
                 const float* __restrict__ s2, const float* __restrict__ s3,
                 float* __restrict__ d0, float* __restrict__ d1,
                 float* __restrict__ d2, float* __restrict__ d3)
{
    const float* src; float* dst; int n4;
    switch (blockIdx.y) {
        case 0: src = s0; dst = d0; n4 = (BATCH * KDIM) / 4; break;
        case 1: src = s1; dst = d1; n4 = (BATCH * KDIM) / 4; break;
        case 2: src = s2; dst = d2; n4 = (FH * KDIM) / 4; break;
        default: src = s3; dst = d3; n4 = (FH * KDIM) / 4; break;
    }
    int i = blockIdx.x * blockDim.x + threadIdx.x;
    int stride = gridDim.x * blockDim.x;
    for (; i < n4; i += stride) {
        float4 v = ((const float4*)src)[i];
        v.x = to_tf32(v.x); v.y = to_tf32(v.y);
        v.z = to_tf32(v.z); v.w = to_tf32(v.w);
        ((float4*)dst)[i] = v;
    }
}

// ---------------------------------------------------------------------------
// GEMM: out[m,n] = sum_k A[m,k] * W[n,k]  (mma.sync tf32 + ldmatrix + cp.async)
// CTA tile 128x256x64, 2 stages, 8 warps (2x4), warp tile 64x64.
// This is the R5 configuration — measured at the legacy tensor-pipe ceiling.
// ---------------------------------------------------------------------------
#define BM 128
#define BN 256
#define BK 64
#define NCHUNK (KDIM / BK)                 // 16
#define ROWW  (BK + 4)                     // 68 floats per smem row
#define A_BYTES (BM * ROWW * 4)            // 34816
#define B_BYTES (BN * ROWW * 4)            // 69632
#define STAGE_BYTES (A_BYTES + B_BYTES)    // 104448
#define SMEM_TOTAL (2 * STAGE_BYTES)       // 208896

__device__ __forceinline__ uint32_t smem_u32(const void* p) {
    uint32_t a;
    asm("{ .reg .u64 t; cvta.to.shared.u64 t, %1; cvt.u32.u64 %0, t; }" : "=r"(a) : "l"(p));
    return a;
}

__device__ __forceinline__ void cp16(uint32_t saddr, const void* g) {
    asm volatile("cp.async.cg.shared.global [%0], [%1], 16;" :: "r"(saddr), "l"(g));
}
#define CP_COMMIT() asm volatile("cp.async.commit_group;" ::: "memory")
#define CP_WAIT_1() asm volatile("cp.async.wait_group 1;" ::: "memory")

__device__ __forceinline__ void ldsm4(uint32_t& r0, uint32_t& r1, uint32_t& r2, uint32_t& r3,
                                      uint32_t addr) {
    asm volatile("ldmatrix.sync.aligned.m8n8.x4.shared.b16 {%0,%1,%2,%3}, [%4];"
                 : "=r"(r0), "=r"(r1), "=r"(r2), "=r"(r3) : "r"(addr));
}

__device__ __forceinline__ void mma_tf32(float c[4], const uint32_t a[4], const uint32_t b[2]) {
    asm volatile(
        "mma.sync.aligned.m16n8k8.row.col.f32.tf32.tf32.f32 "
        "{%0,%1,%2,%3}, {%4,%5,%6,%7}, {%8,%9}, {%0,%1,%2,%3};"
        : "+f"(c[0]), "+f"(c[1]), "+f"(c[2]), "+f"(c[3])
        : "r"(a[0]), "r"(a[1]), "r"(a[2]), "r"(a[3]),
          "r"(b[0]), "r"(b[1]));
}

__global__ void __launch_bounds__(256, 1)
gemm_tc_kernel(const float* __restrict__ gA, const float* __restrict__ gH,
               const float* __restrict__ gWi, const float* __restrict__ gWh)
{
    extern __shared__ char smem[];
    const uint32_t sbase = smem_u32(smem);

    const float* A   = (blockIdx.z == 0) ? gA  : gH;
    const float* W   = (blockIdx.z == 0) ? gWi : gWh;
    float*       out = (blockIdx.z == 0) ? g_ig : g_hg;

    const int tid  = threadIdx.x;
    const int wid  = tid >> 5;
    const int lane = tid & 31;
    const int wm   = wid >> 2;     // 0..1 -> 64-row slab
    const int wn   = wid & 3;      // 0..3 -> 64-col slab
    const int m0   = blockIdx.y * BM;
    const int n0   = blockIdx.x * BN;

    // cp.async loader mapping: 16 float4 chunks per row
    const int ldrow = tid >> 4;
    const int ldc4  = tid & 15;

    auto load_stage = [&](int st, int c) {
        const uint32_t sA = sbase + st * STAGE_BYTES;
        const uint32_t sB = sA + A_BYTES;
        const int kt = c * BK;
        #pragma unroll
        for (int i = 0; i < 8; i++) {
            int row = ldrow + i * 16;
            cp16(sA + (row * ROWW + ldc4 * 4) * 4,
                 &A[(size_t)(m0 + row) * KDIM + kt + ldc4 * 4]);
        }
        #pragma unroll
        for (int i = 0; i < 16; i++) {
            int row = ldrow + i * 16;
            cp16(sB + (row * ROWW + ldc4 * 4) * 4,
                 &W[(size_t)(n0 + row) * KDIM + kt + ldc4 * 4]);
        }
    };

    // ldmatrix per-lane base offsets (bytes within a stage)
    const int lt  = lane >> 3;
    const int lri = lane & 7;
    uint32_t offA[4];
    {
        int row = wm * 64 + lri + (lt & 1) * 8;
        int col = (lt >> 1) * 4;
        #pragma unroll
        for (int mt = 0; mt < 4; mt++)
            offA[mt] = ((row + mt * 16) * ROWW + col) * 4;
    }
    uint32_t offB[4];
    {
        int row = wn * 64 + lri + (lt >> 1) * 8;
        int col = (lt & 1) * 4;
        #pragma unroll
        for (int nt2 = 0; nt2 < 4; nt2++)
            offB[nt2] = (uint32_t)A_BYTES + ((row + nt2 * 16) * ROWW + col) * 4;
    }

    float acc[4][8][4];
    #pragma unroll
    for (int mt = 0; mt < 4; mt++)
        #pragma unroll
        for (int nt = 0; nt < 8; nt++)
            #pragma unroll
            for (int r = 0; r < 4; r++)
                acc[mt][nt][r] = 0.f;

    load_stage(0, 0); CP_COMMIT();
    load_stage(1, 1); CP_COMMIT();

    for (int c = 0; c < NCHUNK; c++) {
        CP_WAIT_1();
        __syncthreads();

        const uint32_t sb = sbase + (c & 1) * STAGE_BYTES;

        #pragma unroll
        for (int kk = 0; kk < BK; kk += 8) {
            const uint32_t kb = kk * 4;
            uint32_t af[4][4];
            #pragma unroll
            for (int mt = 0; mt < 4; mt++)
                ldsm4(af[mt][0], af[mt][1], af[mt][2], af[mt][3], sb + offA[mt] + kb);
            uint32_t bf[8][2];
            #pragma unroll
            for (int nt2 = 0; nt2 < 4; nt2++)
                ldsm4(bf[2*nt2][0], bf[2*nt2][1], bf[2*nt2+1][0], bf[2*nt2+1][1],
                      sb + offB[nt2] + kb);
            #pragma unroll
            for (int mt = 0; mt < 4; mt++)
                #pragma unroll
                for (int nt = 0; nt < 8; nt++)
                    mma_tf32(acc[mt][nt], af[mt], bf[nt]);
        }

        __syncthreads();
        if (c + 2 < NCHUNK) load_stage(c & 1, c + 2);
        CP_COMMIT();
    }

    // epilogue
    #pragma unroll
    for (int mt = 0; mt < 4; mt++) {
        int row0 = m0 + wm * 64 + mt * 16 + (lane >> 2);
        #pragma unroll
        for (int nt = 0; nt < 8; nt++) {
            int col0 = n0 + wn * 64 + nt * 8 + 2 * (lane & 3);
            *(float2*)&out[(size_t)row0 * FH + col0] =
                make_float2(acc[mt][nt][0], acc[mt][nt][1]);
            *(float2*)&out[(size_t)(row0 + 8) * FH + col0] =
                make_float2(acc[mt][nt][2], acc[mt][nt][3]);
        }
    }
}

// ---------------------------------------------------------------------------
// Fused LayerNorm + LSTM gates + cell LayerNorm. Register-resident gates,
// single combined float4 reduction for (sum_i, sq_i, sum_h, sq_h).
// ---------------------------------------------------------------------------
__device__ __forceinline__ float sigmoidf_(float x) {
    return 1.f / (1.f + expf(-x));
}

__device__ __forceinline__ float4 block_sum4(float4 v, float4* sh) {
    #pragma unroll
    for (int o = 16; o > 0; o >>= 1) {
        v.x += __shfl_down_sync(0xffffffffu, v.x, o);
        v.y += __shfl_down_sync(0xffffffffu, v.y, o);
        v.z += __shfl_down_sync(0xffffffffu, v.z, o);
        v.w += __shfl_down_sync(0xffffffffu, v.w, o);
    }
    int lane = threadIdx.x & 31, w = threadIdx.x >> 5;
    if (lane == 0) sh[w] = v;
    __syncthreads();
    if (w == 0) {
        float4 t = (lane < 8) ? sh[lane] : make_float4(0.f, 0.f, 0.f, 0.f);
        #pragma unroll
        for (int o = 4; o > 0; o >>= 1) {
            t.x += __shfl_down_sync(0xffffffffu, t.x, o);
            t.y += __shfl_down_sync(0xffffffffu, t.y, o);
            t.z += __shfl_down_sync(0xffffffffu, t.z, o);
            t.w += __shfl_down_sync(0xffffffffu, t.w, o);
        }
        if (lane == 0) sh[0] = t;
    }
    __syncthreads();
    return sh[0];
}

__device__ __forceinline__ float2 block_sum2(float2 v, float2* sh) {
    #pragma unroll
    for (int o = 16; o > 0; o >>= 1) {
        v.x += __shfl_down_sync(0xffffffffu, v.x, o);
        v.y += __shfl_down_sync(0xffffffffu, v.y, o);
    }
    int lane = threadIdx.x & 31, w = threadIdx.x >> 5;
    if (lane == 0) sh[w] = v;
    __syncthreads();
    if (w == 0) {
        float2 t = (lane < 8) ? sh[lane] : make_float2(0.f, 0.f);
        #pragma unroll
        for (int o = 4; o > 0; o >>= 1) {
            t.x += __shfl_down_sync(0xffffffffu, t.x, o);
            t.y += __shfl_down_sync(0xffffffffu, t.y, o);
        }
        if (lane == 0) sh[0] = t;
    }
    __syncthreads();
    return sh[0];
}

__global__ void __launch_bounds__(256)
fuse_kernel(const float* __restrict__ cx,
            const float* __restrict__ ln_i_w, const float* __restrict__ ln_i_b,
            const float* __restrict__ ln_h_w, const float* __restrict__ ln_h_b,
            const float* __restrict__ ln_c_w, const float* __restrict__ ln_c_b,
            float* __restrict__ out)
{
    const int b   = blockIdx.x;
    const int tid = threadIdx.x;
    const float4* ig4 = (const float4*)(g_ig + (size_t)b * FH);
    const float4* hg4 = (const float4*)(g_hg + (size_t)b * FH);

    __shared__ float4 red4[8];
    __shared__ float2 red_c[8];

    float4 vi[4], vh[4];
    float4 s = make_float4(0.f, 0.f, 0.f, 0.f);   // sum_i, sq_i, sum_h, sq_h
    #pragma unroll
    for (int p = 0; p < 4; p++) {
        int j = tid + p * 256;
        float4 a = ig4[j], c = hg4[j];
        vi[p] = a; vh[p] = c;
        s.x += a.x + a.y + a.z + a.w;
        s.y += a.x*a.x + a.y*a.y + a.z*a.z + a.w*a.w;
        s.z += c.x + c.y + c.z + c.w;
        s.w += c.x*c.x + c.y*c.y + c.z*c.z + c.w*c.w;
    }
    float4 r = block_sum4(s, red4);

    const float inv_fh = 1.f / (float)FH;
    float mu_i = r.x * inv_fh;
    float rs_i = rsqrtf(r.y * inv_fh - mu_i * mu_i + 1e-5f);
    float mu_h = r.z * inv_fh;
    float rs_h = rsqrtf(r.w * inv_fh - mu_h * mu_h + 1e-5f);

    // gate p for h = 4t..4t+3  (p: 0=i, 1=f, 2=g, 3=o)
    float4 g[4];
    #pragma unroll
    for (int p = 0; p < 4; p++) {
        int j = tid + p * 256;
        float4 wi = ((const float4*)ln_i_w)[j], bi = ((const float4*)ln_i_b)[j];
        float4 wh = ((const float4*)ln_h_w)[j], bh = ((const float4*)ln_h_b)[j];
        float4 a = vi[p], c = vh[p];
        g[p].x = (a.x - mu_i) * rs_i * wi.x + bi.x + (c.x - mu_h) * rs_h * wh.x + bh.x;
        g[p].y = (a.y - mu_i) * rs_i * wi.y + bi.y + (c.y - mu_h) * rs_h * wh.y + bh.y;
        g[p].z = (a.z - mu_i) * rs_i * wi.z + bi.z + (c.z - mu_h) * rs_h * wh.z + bh.z;
        g[p].w = (a.w - mu_i) * rs_i * wi.w + bi.w + (c.w - mu_h) * rs_h * wh.w + bh.w;
    }

    float4 c4 = ((const float4*)cx)[b * 256 + tid];

    float4 cv;
    cv.x = sigmoidf_(g[1].x) * c4.x + sigmoidf_(g[0].x) * tanhf(g[2].x);
    cv.y = sigmoidf_(g[1].y) * c4.y + sigmoidf_(g[0].y) * tanhf(g[2].y);
    cv.z = sigmoidf_(g[1].z) * c4.z + sigmoidf_(g[0].z) * tanhf(g[2].z);
    cv.w = sigmoidf_(g[1].w) * c4.w + sigmoidf_(g[0].w) * tanhf(g[2].w);

    float2 sc = make_float2(cv.x + cv.y + cv.z + cv.w,
                            cv.x*cv.x + cv.y*cv.y + cv.z*cv.z + cv.w*cv.w);
    float2 rc = block_sum2(sc, red_c);
    const float inv_h = 1.f / (float)HDIM;
    float mu_c = rc.x * inv_h;
    float rs_c = rsqrtf(rc.y * inv_h - mu_c * mu_c + 1e-5f);

    float4 wc = ((const float4*)ln_c_w)[tid], bc = ((const float4*)ln_c_b)[tid];
    float4 cy, hy;
    cy.x = (cv.x - mu_c) * rs_c * wc.x + bc.x;  hy.x = sigmoidf_(g[3].x) * tanhf(cy.x);
    cy.y = (cv.y - mu_c) * rs_c * wc.y + bc.y;  hy.y = sigmoidf_(g[3].y) * tanhf(cy.y);
    cy.z = (cv.z - mu_c) * rs_c * wc.z + bc.z;  hy.z = sigmoidf_(g[3].z) * tanhf(cy.z);
    cy.w = (cv.w - mu_c) * rs_c * wc.w + bc.w;  hy.w = sigmoidf_(g[3].w) * tanhf(cy.w);

    ((float4*)out)[(size_t)b * 256 + tid] = hy;
    ((float4*)out)[(size_t)BATCH * 256 + (size_t)b * 256 + tid] = cy;
}

// ---------------------------------------------------------------------------
extern "C" void kernel_launch(void* const* d_in, const int* in_sizes, int n_in,
                              void* d_out, int out_size)
{
    const float* input  = (const float*)d_in[0];
    const float* hx     = (const float*)d_in[1];
    const float* cx     = (const float*)d_in[2];
    const float* wih    = (const float*)d_in[3];
    const float* whh    = (const float*)d_in[4];
    const float* ln_i_w = (const float*)d_in[5];
    const float* ln_i_b = (const float*)d_in[6];
    const float* ln_h_w = (const float*)d_in[7];
    const float* ln_h_b = (const float*)d_in[8];
    const float* ln_c_w = (const float*)d_in[9];
    const float* ln_c_b = (const float*)d_in[10];
    float* out = (float*)d_out;

    cudaFuncSetAttribute(gemm_tc_kernel,
                         cudaFuncAttributeMaxDynamicSharedMemorySize, SMEM_TOTAL);

    float *dA, *dH, *dWi, *dWh;
    cudaGetSymbolAddress((void**)&dA,  g_A);
    cudaGetSymbolAddress((void**)&dH,  g_H);
    cudaGetSymbolAddress((void**)&dWi, g_Wi);
    cudaGetSymbolAddress((void**)&dWh, g_Wh);

    round_all_kernel<<<dim3(296, 4), 256>>>(input, hx, wih, whh, dA, dH, dWi, dWh);

    dim3 grid(FH / BN, BATCH / BM, 2);
    gemm_tc_kernel<<<grid, 256, SMEM_TOTAL>>>(dA, dH, dWi, dWh);
    fuse_kernel<<<BATCH, 256>>>(cx, ln_i_w, ln_i_b, ln_h_w, ln_h_b, ln_c_w, ln_c_b, out);
}

// round 10
// speedup vs baseline: 2.5033x; 1.5566x over previous
#include <cuda_runtime.h>
#include <cuda_fp16.h>
#include <math.h>
#include <stdint.h>

#define BATCH 8192
#define KDIM  1024
#define HDIM  1024
#define FH    4096

// Scratch: raw gate pre-activations + fp16 operand copies.
__device__ float g_ig[(size_t)BATCH * FH];
__device__ float g_hg[(size_t)BATCH * FH];
__device__ __half g_A [(size_t)BATCH * KDIM];
__device__ __half g_H [(size_t)BATCH * KDIM];
__device__ __half g_Wi[(size_t)FH * KDIM];
__device__ __half g_Wh[(size_t)FH * KDIM];

// ---------------------------------------------------------------------------
// fp32 -> fp16 (RN) conversion, all 4 tensors in one launch.
// fp16 mantissa = 10 bits = tf32 mantissa: same precision as the tf32 path.
// ---------------------------------------------------------------------------
__global__ void __launch_bounds__(256)
cvt_fp16_kernel(const float* __restrict__ s0, const float* __restrict__ s1,
                const float* __restrict__ s2, const float* __restrict__ s3,
                __half* __restrict__ d0, __half* __restrict__ d1,
                __half* __restrict__ d2, __half* __restrict__ d3)
{
    const float* src; __half* dst; int n4;
    switch (blockIdx.y) {
        case 0: src = s0; dst = d0; n4 = (BATCH * KDIM) / 4; break;
        case 1: src = s1; dst = d1; n4 = (BATCH * KDIM) / 4; break;
        case 2: src = s2; dst = d2; n4 = (FH * KDIM) / 4; break;
        default: src = s3; dst = d3; n4 = (FH * KDIM) / 4; break;
    }
    int i = blockIdx.x * blockDim.x + threadIdx.x;
    int stride = gridDim.x * blockDim.x;
    for (; i < n4; i += stride) {
        float4 v = ((const float4*)src)[i];
        __half2 lo = __floats2half2_rn(v.x, v.y);
        __half2 hi = __floats2half2_rn(v.z, v.w);
        uint2 p;
        p.x = *(uint32_t*)&lo;
        p.y = *(uint32_t*)&hi;
        ((uint2*)dst)[i] = p;
    }
}

// ---------------------------------------------------------------------------
// GEMM: out[m,n] = sum_k A[m,k] * W[n,k]  via mma.sync m16n8k16.f16 (fp32 acc)
// CTA tile 128x256, K-chunk 64, 3 stages, 8 warps (2x4), warp tile 64x64.
// One barrier per chunk: wait -> sync -> load(c+2) -> commit -> compute.
// ---------------------------------------------------------------------------
#define BM 128
#define BN 256
#define KC 64
#define NCHUNK (KDIM / KC)                 // 16
#define ROWB  144                          // 64 fp16 = 128B data + 16B pad
#define A_B   (BM * ROWB)                  // 18432
#define B_B   (BN * ROWB)                  // 36864
#define STAGE_BYTES (A_B + B_B)            // 55296
#define SMEM_TOTAL (3 * STAGE_BYTES)       // 165888
#define NTHREADS 256

__device__ __forceinline__ uint32_t smem_u32(const void* p) {
    uint32_t a;
    asm("{ .reg .u64 t; cvta.to.shared.u64 t, %1; cvt.u32.u64 %0, t; }" : "=r"(a) : "l"(p));
    return a;
}

__device__ __forceinline__ void cp16(uint32_t saddr, const void* g) {
    asm volatile("cp.async.cg.shared.global [%0], [%1], 16;" :: "r"(saddr), "l"(g));
}
#define CP_COMMIT() asm volatile("cp.async.commit_group;" ::: "memory")
#define CP_WAIT_1() asm volatile("cp.async.wait_group 1;" ::: "memory")

__device__ __forceinline__ void ldsm4(uint32_t& r0, uint32_t& r1, uint32_t& r2, uint32_t& r3,
                                      uint32_t addr) {
    asm volatile("ldmatrix.sync.aligned.m8n8.x4.shared.b16 {%0,%1,%2,%3}, [%4];"
                 : "=r"(r0), "=r"(r1), "=r"(r2), "=r"(r3) : "r"(addr));
}

__device__ __forceinline__ void mma_f16(float c[4], const uint32_t a[4], const uint32_t b[2]) {
    asm volatile(
        "mma.sync.aligned.m16n8k16.row.col.f32.f16.f16.f32 "
        "{%0,%1,%2,%3}, {%4,%5,%6,%7}, {%8,%9}, {%0,%1,%2,%3};"
        : "+f"(c[0]), "+f"(c[1]), "+f"(c[2]), "+f"(c[3])
        : "r"(a[0]), "r"(a[1]), "r"(a[2]), "r"(a[3]),
          "r"(b[0]), "r"(b[1]));
}

__global__ void __launch_bounds__(NTHREADS, 1)
gemm_f16_kernel(const __half* __restrict__ gA, const __half* __restrict__ gH,
                const __half* __restrict__ gWi, const __half* __restrict__ gWh)
{
    extern __shared__ char smem[];
    const uint32_t sbase = smem_u32(smem);

    const __half* A  = (blockIdx.z == 0) ? gA  : gH;
    const __half* W  = (blockIdx.z == 0) ? gWi : gWh;
    float*       out = (blockIdx.z == 0) ? g_ig : g_hg;

    const int tid  = threadIdx.x;
    const int wid  = tid >> 5;
    const int lane = tid & 31;
    const int wm   = wid >> 2;     // 0..1 -> 64-row slab
    const int wn   = wid & 3;      // 0..3 -> 64-col slab
    const int m0   = blockIdx.y * BM;
    const int n0   = blockIdx.x * BN;

    // cp.async loader: 64 fp16 per row = 8 x 16B chunks
    const int ldrow = tid >> 3;    // 0..31
    const int ldc   = tid & 7;     // chunk in row

    auto load_stage = [&](int st, int c) {
        const uint32_t sA = sbase + st * STAGE_BYTES;
        const uint32_t sB = sA + A_B;
        const int kt = c * KC;
        #pragma unroll
        for (int i = 0; i < 4; i++) {               // A: 128 rows x 8 chunks
            int row = ldrow + i * 32;
            cp16(sA + row * ROWB + ldc * 16,
                 &A[(size_t)(m0 + row) * KDIM + kt + ldc * 8]);
        }
        #pragma unroll
        for (int i = 0; i < 8; i++) {               // B: 256 rows x 8 chunks
            int row = ldrow + i * 32;
            cp16(sB + row * ROWB + ldc * 16,
                 &W[(size_t)(n0 + row) * KDIM + kt + ldc * 8]);
        }
    };

    // ldmatrix lane addressing (verified by R8's k16 path):
    // lanes 0-15 -> rows at k0; lanes 16-31 -> same rows at k+8 (16B).
    const int lrow = lane & 15;
    const int lkof = (lane >> 4) * 16;
    uint32_t offA[4], offB[4];
    #pragma unroll
    for (int mt = 0; mt < 4; mt++)
        offA[mt] = (wm * 64 + mt * 16 + lrow) * ROWB + lkof;
    #pragma unroll
    for (int p = 0; p < 4; p++)
        offB[p] = (uint32_t)A_B + (wn * 64 + p * 16 + lrow) * ROWB + lkof;

    float acc[4][8][4];
    #pragma unroll
    for (int mt = 0; mt < 4; mt++)
        #pragma unroll
        for (int nt = 0; nt < 8; nt++)
            #pragma unroll
            for (int r = 0; r < 4; r++)
                acc[mt][nt][r] = 0.f;

    load_stage(0, 0); CP_COMMIT();
    load_stage(1, 1); CP_COMMIT();

    int st = 0;
    for (int c = 0; c < NCHUNK; c++) {
        CP_WAIT_1();
        __syncthreads();   // chunk c ready; stage (c+2)%3 free (compute of c-1 done)

        int st2 = st + 2; if (st2 >= 3) st2 -= 3;
        if (c + 2 < NCHUNK) load_stage(st2, c + 2);
        CP_COMMIT();

        const uint32_t sb = sbase + st * STAGE_BYTES;

        #pragma unroll
        for (int ks = 0; ks < 4; ks++) {           // four k16 steps per chunk
            const uint32_t kb = ks * 32;           // 16 fp16 = 32 bytes

            uint32_t af[4][4];
            #pragma unroll
            for (int mt = 0; mt < 4; mt++)
                ldsm4(af[mt][0], af[mt][1], af[mt][2], af[mt][3], sb + offA[mt] + kb);
            uint32_t bf[8][2];
            #pragma unroll
            for (int p = 0; p < 4; p++)
                ldsm4(bf[2*p][0], bf[2*p+1][0], bf[2*p][1], bf[2*p+1][1],
                      sb + offB[p] + kb);
            #pragma unroll
            for (int mt = 0; mt < 4; mt++)
                #pragma unroll
                for (int nt = 0; nt < 8; nt++)
                    mma_f16(acc[mt][nt], af[mt], bf[nt]);
        }

        if (++st >= 3) st -= 3;
    }

    // epilogue (same c-fragment layout as k8)
    #pragma unroll
    for (int mt = 0; mt < 4; mt++) {
        int row0 = m0 + wm * 64 + mt * 16 + (lane >> 2);
        #pragma unroll
        for (int nt = 0; nt < 8; nt++) {
            int col0 = n0 + wn * 64 + nt * 8 + 2 * (lane & 3);
            *(float2*)&out[(size_t)row0 * FH + col0] =
                make_float2(acc[mt][nt][0], acc[mt][nt][1]);
            *(float2*)&out[(size_t)(row0 + 8) * FH + col0] =
                make_float2(acc[mt][nt][2], acc[mt][nt][3]);
        }
    }
}

// ---------------------------------------------------------------------------
// Fused LayerNorm + LSTM gates + cell LayerNorm (R9: register-resident,
// combined 4-way reduction).
// ---------------------------------------------------------------------------
__device__ __forceinline__ float sigmoidf_(float x) {
    return 1.f / (1.f + expf(-x));
}

__device__ __forceinline__ float4 block_sum4(float4 v, float4* sh) {
    #pragma unroll
    for (int o = 16; o > 0; o >>= 1) {
        v.x += __shfl_down_sync(0xffffffffu, v.x, o);
        v.y += __shfl_down_sync(0xffffffffu, v.y, o);
        v.z += __shfl_down_sync(0xffffffffu, v.z, o);
        v.w += __shfl_down_sync(0xffffffffu, v.w, o);
    }
    int lane = threadIdx.x & 31, w = threadIdx.x >> 5;
    if (lane == 0) sh[w] = v;
    __syncthreads();
    if (w == 0) {
        float4 t = (lane < 8) ? sh[lane] : make_float4(0.f, 0.f, 0.f, 0.f);
        #pragma unroll
        for (int o = 4; o > 0; o >>= 1) {
            t.x += __shfl_down_sync(0xffffffffu, t.x, o);
            t.y += __shfl_down_sync(0xffffffffu, t.y, o);
            t.z += __shfl_down_sync(0xffffffffu, t.z, o);
            t.w += __shfl_down_sync(0xffffffffu, t.w, o);
        }
        if (lane == 0) sh[0] = t;
    }
    __syncthreads();
    return sh[0];
}

__device__ __forceinline__ float2 block_sum2(float2 v, float2* sh) {
    #pragma unroll
    for (int o = 16; o > 0; o >>= 1) {
        v.x += __shfl_down_sync(0xffffffffu, v.x, o);
        v.y += __shfl_down_sync(0xffffffffu, v.y, o);
    }
    int lane = threadIdx.x & 31, w = threadIdx.x >> 5;
    if (lane == 0) sh[w] = v;
    __syncthreads();
    if (w == 0) {
        float2 t = (lane < 8) ? sh[lane] : make_float2(0.f, 0.f);
        #pragma unroll
        for (int o = 4; o > 0; o >>= 1) {
            t.x += __shfl_down_sync(0xffffffffu, t.x, o);
            t.y += __shfl_down_sync(0xffffffffu, t.y, o);
        }
        if (lane == 0) sh[0] = t;
    }
    __syncthreads();
    return sh[0];
}

__global__ void __launch_bounds__(256)
fuse_kernel(const float* __restrict__ cx,
            const float* __restrict__ ln_i_w, const float* __restrict__ ln_i_b,
            const float* __restrict__ ln_h_w, const float* __restrict__ ln_h_b,
            const float* __restrict__ ln_c_w, const float* __restrict__ ln_c_b,
            float* __restrict__ out)
{
    const int b   = blockIdx.x;
    const int tid = threadIdx.x;
    const float4* ig4 = (const float4*)(g_ig + (size_t)b * FH);
    const float4* hg4 = (const float4*)(g_hg + (size_t)b * FH);

    __shared__ float4 red4[8];
    __shared__ float2 red_c[8];

    float4 vi[4], vh[4];
    float4 s = make_float4(0.f, 0.f, 0.f, 0.f);
    #pragma unroll
    for (int p = 0; p < 4; p++) {
        int j = tid + p * 256;
        float4 a = ig4[j], c = hg4[j];
        vi[p] = a; vh[p] = c;
        s.x += a.x + a.y + a.z + a.w;
        s.y += a.x*a.x + a.y*a.y + a.z*a.z + a.w*a.w;
        s.z += c.x + c.y + c.z + c.w;
        s.w += c.x*c.x + c.y*c.y + c.z*c.z + c.w*c.w;
    }
    float4 r = block_sum4(s, red4);

    const float inv_fh = 1.f / (float)FH;
    float mu_i = r.x * inv_fh;
    float rs_i = rsqrtf(r.y * inv_fh - mu_i * mu_i + 1e-5f);
    float mu_h = r.z * inv_fh;
    float rs_h = rsqrtf(r.w * inv_fh - mu_h * mu_h + 1e-5f);

    float4 g[4];
    #pragma unroll
    for (int p = 0; p < 4; p++) {
        int j = tid + p * 256;
        float4 wi = ((const float4*)ln_i_w)[j], bi = ((const float4*)ln_i_b)[j];
        float4 wh = ((const float4*)ln_h_w)[j], bh = ((const float4*)ln_h_b)[j];
        float4 a = vi[p], c = vh[p];
        g[p].x = (a.x - mu_i) * rs_i * wi.x + bi.x + (c.x - mu_h) * rs_h * wh.x + bh.x;
        g[p].y = (a.y - mu_i) * rs_i * wi.y + bi.y + (c.y - mu_h) * rs_h * wh.y + bh.y;
        g[p].z = (a.z - mu_i) * rs_i * wi.z + bi.z + (c.z - mu_h) * rs_h * wh.z + bh.z;
        g[p].w = (a.w - mu_i) * rs_i * wi.w + bi.w + (c.w - mu_h) * rs_h * wh.w + bh.w;
    }

    float4 c4 = ((const float4*)cx)[b * 256 + tid];

    float4 cv;
    cv.x = sigmoidf_(g[1].x) * c4.x + sigmoidf_(g[0].x) * tanhf(g[2].x);
    cv.y = sigmoidf_(g[1].y) * c4.y + sigmoidf_(g[0].y) * tanhf(g[2].y);
    cv.z = sigmoidf_(g[1].z) * c4.z + sigmoidf_(g[0].z) * tanhf(g[2].z);
    cv.w = sigmoidf_(g[1].w) * c4.w + sigmoidf_(g[0].w) * tanhf(g[2].w);

    float2 sc = make_float2(cv.x + cv.y + cv.z + cv.w,
                            cv.x*cv.x + cv.y*cv.y + cv.z*cv.z + cv.w*cv.w);
    float2 rc = block_sum2(sc, red_c);
    const float inv_h = 1.f / (float)HDIM;
    float mu_c = rc.x * inv_h;
    float rs_c = rsqrtf(rc.y * inv_h - mu_c * mu_c + 1e-5f);

    float4 wc = ((const float4*)ln_c_w)[tid], bc = ((const float4*)ln_c_b)[tid];
    float4 cy, hy;
    cy.x = (cv.x - mu_c) * rs_c * wc.x + bc.x;  hy.x = sigmoidf_(g[3].x) * tanhf(cy.x);
    cy.y = (cv.y - mu_c) * rs_c * wc.y + bc.y;  hy.y = sigmoidf_(g[3].y) * tanhf(cy.y);
    cy.z = (cv.z - mu_c) * rs_c * wc.z + bc.z;  hy.z = sigmoidf_(g[3].z) * tanhf(cy.z);
    cy.w = (cv.w - mu_c) * rs_c * wc.w + bc.w;  hy.w = sigmoidf_(g[3].w) * tanhf(cy.w);

    ((float4*)out)[(size_t)b * 256 + tid] = hy;
    ((float4*)out)[(size_t)BATCH * 256 + (size_t)b * 256 + tid] = cy;
}

// ---------------------------------------------------------------------------
extern "C" void kernel_launch(void* const* d_in, const int* in_sizes, int n_in,
                              void* d_out, int out_size)
{
    const float* input  = (const float*)d_in[0];
    const float* hx     = (const float*)d_in[1];
    const float* cx     = (const float*)d_in[2];
    const float* wih    = (const float*)d_in[3];
    const float* whh    = (const float*)d_in[4];
    const float* ln_i_w = (const float*)d_in[5];
    const float* ln_i_b = (const float*)d_in[6];
    const float* ln_h_w = (const float*)d_in[7];
    const float* ln_h_b = (const float*)d_in[8];
    const float* ln_c_w = (const float*)d_in[9];
    const float* ln_c_b = (const float*)d_in[10];
    float* out = (float*)d_out;

    cudaFuncSetAttribute(gemm_f16_kernel,
                         cudaFuncAttributeMaxDynamicSharedMemorySize, SMEM_TOTAL);

    __half *dA, *dH, *dWi, *dWh;
    cudaGetSymbolAddress((void**)&dA,  g_A);
    cudaGetSymbolAddress((void**)&dH,  g_H);
    cudaGetSymbolAddress((void**)&dWi, g_Wi);
    cudaGetSymbolAddress((void**)&dWh, g_Wh);

    cvt_fp16_kernel<<<dim3(296, 4), 256>>>(input, hx, wih, whh, dA, dH, dWi, dWh);

    dim3 grid(FH / BN, BATCH / BM, 2);
    gemm_f16_kernel<<<grid, 256, SMEM_TOTAL>>>(dA, dH, dWi, dWh);
    fuse_kernel<<<BATCH, 256>>>(cx, ln_i_w, ln_i_b, ln_h_w, ln_h_b, ln_c_w, ln_c_b, out);
}

// round 11
// speedup vs baseline: 2.6320x; 1.0514x over previous
#include <cuda_runtime.h>
#include <cuda_fp16.h>
#include <math.h>
#include <stdint.h>

#define BATCH 8192
#define KDIM  1024
#define HDIM  1024
#define FH    4096

// Scratch: fp16 gate pre-activations + fp16 operand copies.
__device__ __half g_ig[(size_t)BATCH * FH];
__device__ __half g_hg[(size_t)BATCH * FH];
__device__ __half g_A [(size_t)BATCH * KDIM];
__device__ __half g_H [(size_t)BATCH * KDIM];
__device__ __half g_Wi[(size_t)FH * KDIM];
__device__ __half g_Wh[(size_t)FH * KDIM];

// ---------------------------------------------------------------------------
// fp32 -> fp16 (RN) conversion, all 4 tensors in one launch.
// ---------------------------------------------------------------------------
__global__ void __launch_bounds__(256)
cvt_fp16_kernel(const float* __restrict__ s0, const float* __restrict__ s1,
                const float* __restrict__ s2, const float* __restrict__ s3,
                __half* __restrict__ d0, __half* __restrict__ d1,
                __half* __restrict__ d2, __half* __restrict__ d3)
{
    const float* src; __half* dst; int n4;
    switch (blockIdx.y) {
        case 0: src = s0; dst = d0; n4 = (BATCH * KDIM) / 4; break;
        case 1: src = s1; dst = d1; n4 = (BATCH * KDIM) / 4; break;
        case 2: src = s2; dst = d2; n4 = (FH * KDIM) / 4; break;
        default: src = s3; dst = d3; n4 = (FH * KDIM) / 4; break;
    }
    int i = blockIdx.x * blockDim.x + threadIdx.x;
    int stride = gridDim.x * blockDim.x;
    for (; i < n4; i += stride) {
        float4 v = ((const float4*)src)[i];
        __half2 lo = __floats2half2_rn(v.x, v.y);
        __half2 hi = __floats2half2_rn(v.z, v.w);
        uint2 p;
        p.x = *(uint32_t*)&lo;
        p.y = *(uint32_t*)&hi;
        ((uint2*)dst)[i] = p;
    }
}

// ---------------------------------------------------------------------------
// GEMM: out[m,n] = sum_k A[m,k] * W[n,k]  via mma.sync m16n8k16.f16 (fp32 acc)
// CTA tile 128x256, K-chunk 64, 3 stages, 8 warps (2x4), warp tile 64x64.
// fp16 epilogue stores.
// ---------------------------------------------------------------------------
#define BM 128
#define BN 256
#define KC 64
#define NCHUNK (KDIM / KC)                 // 16
#define ROWB  144                          // 64 fp16 = 128B data + 16B pad
#define A_B   (BM * ROWB)                  // 18432
#define B_B   (BN * ROWB)                  // 36864
#define STAGE_BYTES (A_B + B_B)            // 55296
#define SMEM_TOTAL (3 * STAGE_BYTES)       // 165888
#define NTHREADS 256

__device__ __forceinline__ uint32_t smem_u32(const void* p) {
    uint32_t a;
    asm("{ .reg .u64 t; cvta.to.shared.u64 t, %1; cvt.u32.u64 %0, t; }" : "=r"(a) : "l"(p));
    return a;
}

__device__ __forceinline__ void cp16(uint32_t saddr, const void* g) {
    asm volatile("cp.async.cg.shared.global [%0], [%1], 16;" :: "r"(saddr), "l"(g));
}
#define CP_COMMIT() asm volatile("cp.async.commit_group;" ::: "memory")
#define CP_WAIT_1() asm volatile("cp.async.wait_group 1;" ::: "memory")

__device__ __forceinline__ void ldsm4(uint32_t& r0, uint32_t& r1, uint32_t& r2, uint32_t& r3,
                                      uint32_t addr) {
    asm volatile("ldmatrix.sync.aligned.m8n8.x4.shared.b16 {%0,%1,%2,%3}, [%4];"
                 : "=r"(r0), "=r"(r1), "=r"(r2), "=r"(r3) : "r"(addr));
}

__device__ __forceinline__ void mma_f16(float c[4], const uint32_t a[4], const uint32_t b[2]) {
    asm volatile(
        "mma.sync.aligned.m16n8k16.row.col.f32.f16.f16.f32 "
        "{%0,%1,%2,%3}, {%4,%5,%6,%7}, {%8,%9}, {%0,%1,%2,%3};"
        : "+f"(c[0]), "+f"(c[1]), "+f"(c[2]), "+f"(c[3])
        : "r"(a[0]), "r"(a[1]), "r"(a[2]), "r"(a[3]),
          "r"(b[0]), "r"(b[1]));
}

__global__ void __launch_bounds__(NTHREADS, 1)
gemm_f16_kernel(const __half* __restrict__ gA, const __half* __restrict__ gH,
                const __half* __restrict__ gWi, const __half* __restrict__ gWh)
{
    extern __shared__ char smem[];
    const uint32_t sbase = smem_u32(smem);

    const __half* A  = (blockIdx.z == 0) ? gA  : gH;
    const __half* W  = (blockIdx.z == 0) ? gWi : gWh;
    __half*      out = (blockIdx.z == 0) ? g_ig : g_hg;

    const int tid  = threadIdx.x;
    const int wid  = tid >> 5;
    const int lane = tid & 31;
    const int wm   = wid >> 2;     // 0..1 -> 64-row slab
    const int wn   = wid & 3;      // 0..3 -> 64-col slab
    const int m0   = blockIdx.y * BM;
    const int n0   = blockIdx.x * BN;

    // cp.async loader: 64 fp16 per row = 8 x 16B chunks
    const int ldrow = tid >> 3;    // 0..31
    const int ldc   = tid & 7;     // chunk in row

    auto load_stage = [&](int st, int c) {
        const uint32_t sA = sbase + st * STAGE_BYTES;
        const uint32_t sB = sA + A_B;
        const int kt = c * KC;
        #pragma unroll
        for (int i = 0; i < 4; i++) {               // A: 128 rows x 8 chunks
            int row = ldrow + i * 32;
            cp16(sA + row * ROWB + ldc * 16,
                 &A[(size_t)(m0 + row) * KDIM + kt + ldc * 8]);
        }
        #pragma unroll
        for (int i = 0; i < 8; i++) {               // B: 256 rows x 8 chunks
            int row = ldrow + i * 32;
            cp16(sB + row * ROWB + ldc * 16,
                 &W[(size_t)(n0 + row) * KDIM + kt + ldc * 8]);
        }
    };

    // ldmatrix lane addressing: lanes 0-15 -> rows at k0; 16-31 -> +16B.
    const int lrow = lane & 15;
    const int lkof = (lane >> 4) * 16;
    uint32_t offA[4], offB[4];
    #pragma unroll
    for (int mt = 0; mt < 4; mt++)
        offA[mt] = (wm * 64 + mt * 16 + lrow) * ROWB + lkof;
    #pragma unroll
    for (int p = 0; p < 4; p++)
        offB[p] = (uint32_t)A_B + (wn * 64 + p * 16 + lrow) * ROWB + lkof;

    float acc[4][8][4];
    #pragma unroll
    for (int mt = 0; mt < 4; mt++)
        #pragma unroll
        for (int nt = 0; nt < 8; nt++)
            #pragma unroll
            for (int r = 0; r < 4; r++)
                acc[mt][nt][r] = 0.f;

    load_stage(0, 0); CP_COMMIT();
    load_stage(1, 1); CP_COMMIT();

    int st = 0;
    for (int c = 0; c < NCHUNK; c++) {
        CP_WAIT_1();
        __syncthreads();

        int st2 = st + 2; if (st2 >= 3) st2 -= 3;
        if (c + 2 < NCHUNK) load_stage(st2, c + 2);
        CP_COMMIT();

        const uint32_t sb = sbase + st * STAGE_BYTES;

        #pragma unroll
        for (int ks = 0; ks < 4; ks++) {
            const uint32_t kb = ks * 32;

            uint32_t af[4][4];
            #pragma unroll
            for (int mt = 0; mt < 4; mt++)
                ldsm4(af[mt][0], af[mt][1], af[mt][2], af[mt][3], sb + offA[mt] + kb);
            uint32_t bf[8][2];
            #pragma unroll
            for (int p = 0; p < 4; p++)
                ldsm4(bf[2*p][0], bf[2*p+1][0], bf[2*p][1], bf[2*p+1][1],
                      sb + offB[p] + kb);
            #pragma unroll
            for (int mt = 0; mt < 4; mt++)
                #pragma unroll
                for (int nt = 0; nt < 8; nt++)
                    mma_f16(acc[mt][nt], af[mt], bf[nt]);
        }

        if (++st >= 3) st -= 3;
    }

    // epilogue: fp16 stores (half the write traffic)
    #pragma unroll
    for (int mt = 0; mt < 4; mt++) {
        int row0 = m0 + wm * 64 + mt * 16 + (lane >> 2);
        #pragma unroll
        for (int nt = 0; nt < 8; nt++) {
            int col0 = n0 + wn * 64 + nt * 8 + 2 * (lane & 3);
            __half2 v0 = __floats2half2_rn(acc[mt][nt][0], acc[mt][nt][1]);
            __half2 v1 = __floats2half2_rn(acc[mt][nt][2], acc[mt][nt][3]);
            *(__half2*)&out[(size_t)row0 * FH + col0]       = v0;
            *(__half2*)&out[(size_t)(row0 + 8) * FH + col0] = v1;
        }
    }
}

// ---------------------------------------------------------------------------
// Fused LayerNorm + LSTM gates + cell LayerNorm. fp16 gate reads.
// ---------------------------------------------------------------------------
__device__ __forceinline__ float sigmoidf_(float x) {
    return 1.f / (1.f + expf(-x));
}

__device__ __forceinline__ float4 block_sum4(float4 v, float4* sh) {
    #pragma unroll
    for (int o = 16; o > 0; o >>= 1) {
        v.x += __shfl_down_sync(0xffffffffu, v.x, o);
        v.y += __shfl_down_sync(0xffffffffu, v.y, o);
        v.z += __shfl_down_sync(0xffffffffu, v.z, o);
        v.w += __shfl_down_sync(0xffffffffu, v.w, o);
    }
    int lane = threadIdx.x & 31, w = threadIdx.x >> 5;
    if (lane == 0) sh[w] = v;
    __syncthreads();
    if (w == 0) {
        float4 t = (lane < 8) ? sh[lane] : make_float4(0.f, 0.f, 0.f, 0.f);
        #pragma unroll
        for (int o = 4; o > 0; o >>= 1) {
            t.x += __shfl_down_sync(0xffffffffu, t.x, o);
            t.y += __shfl_down_sync(0xffffffffu, t.y, o);
            t.z += __shfl_down_sync(0xffffffffu, t.z, o);
            t.w += __shfl_down_sync(0xffffffffu, t.w, o);
        }
        if (lane == 0) sh[0] = t;
    }
    __syncthreads();
    return sh[0];
}

__device__ __forceinline__ float2 block_sum2(float2 v, float2* sh) {
    #pragma unroll
    for (int o = 16; o > 0; o >>= 1) {
        v.x += __shfl_down_sync(0xffffffffu, v.x, o);
        v.y += __shfl_down_sync(0xffffffffu, v.y, o);
    }
    int lane = threadIdx.x & 31, w = threadIdx.x >> 5;
    if (lane == 0) sh[w] = v;
    __syncthreads();
    if (w == 0) {
        float2 t = (lane < 8) ? sh[lane] : make_float2(0.f, 0.f);
        #pragma unroll
        for (int o = 4; o > 0; o >>= 1) {
            t.x += __shfl_down_sync(0xffffffffu, t.x, o);
            t.y += __shfl_down_sync(0xffffffffu, t.y, o);
        }
        if (lane == 0) sh[0] = t;
    }
    __syncthreads();
    return sh[0];
}

__device__ __forceinline__ float4 ld_gates4(const uint2* p, int j) {
    uint2 u = p[j];
    __half2 h0 = *(__half2*)&u.x;
    __half2 h1 = *(__half2*)&u.y;
    float2 f0 = __half22float2(h0);
    float2 f1 = __half22float2(h1);
    return make_float4(f0.x, f0.y, f1.x, f1.y);
}

__global__ void __launch_bounds__(256)
fuse_kernel(const float* __restrict__ cx,
            const float* __restrict__ ln_i_w, const float* __restrict__ ln_i_b,
            const float* __restrict__ ln_h_w, const float* __restrict__ ln_h_b,
            const float* __restrict__ ln_c_w, const float* __restrict__ ln_c_b,
            float* __restrict__ out)
{
    const int b   = blockIdx.x;
    const int tid = threadIdx.x;
    const uint2* ig2 = (const uint2*)(g_ig + (size_t)b * FH);
    const uint2* hg2 = (const uint2*)(g_hg + (size_t)b * FH);

    __shared__ float4 red4[8];
    __shared__ float2 red_c[8];

    float4 vi[4], vh[4];
    float4 s = make_float4(0.f, 0.f, 0.f, 0.f);
    #pragma unroll
    for (int p = 0; p < 4; p++) {
        int j = tid + p * 256;
        float4 a = ld_gates4(ig2, j);
        float4 c = ld_gates4(hg2, j);
        vi[p] = a; vh[p] = c;
        s.x += a.x + a.y + a.z + a.w;
        s.y += a.x*a.x + a.y*a.y + a.z*a.z + a.w*a.w;
        s.z += c.x + c.y + c.z + c.w;
        s.w += c.x*c.x + c.y*c.y + c.z*c.z + c.w*c.w;
    }
    float4 r = block_sum4(s, red4);

    const float inv_fh = 1.f / (float)FH;
    float mu_i = r.x * inv_fh;
    float rs_i = rsqrtf(r.y * inv_fh - mu_i * mu_i + 1e-5f);
    float mu_h = r.z * inv_fh;
    float rs_h = rsqrtf(r.w * inv_fh - mu_h * mu_h + 1e-5f);

    float4 g[4];
    #pragma unroll
    for (int p = 0; p < 4; p++) {
        int j = tid + p * 256;
        float4 wi = ((const float4*)ln_i_w)[j], bi = ((const float4*)ln_i_b)[j];
        float4 wh = ((const float4*)ln_h_w)[j], bh = ((const float4*)ln_h_b)[j];
        float4 a = vi[p], c = vh[p];
        g[p].x = (a.x - mu_i) * rs_i * wi.x + bi.x + (c.x - mu_h) * rs_h * wh.x + bh.x;
        g[p].y = (a.y - mu_i) * rs_i * wi.y + bi.y + (c.y - mu_h) * rs_h * wh.y + bh.y;
        g[p].z = (a.z - mu_i) * rs_i * wi.z + bi.z + (c.z - mu_h) * rs_h * wh.z + bh.z;
        g[p].w = (a.w - mu_i) * rs_i * wi.w + bi.w + (c.w - mu_h) * rs_h * wh.w + bh.w;
    }

    float4 c4 = ((const float4*)cx)[b * 256 + tid];

    float4 cv;
    cv.x = sigmoidf_(g[1].x) * c4.x + sigmoidf_(g[0].x) * tanhf(g[2].x);
    cv.y = sigmoidf_(g[1].y) * c4.y + sigmoidf_(g[0].y) * tanhf(g[2].y);
    cv.z = sigmoidf_(g[1].z) * c4.z + sigmoidf_(g[0].z) * tanhf(g[2].z);
    cv.w = sigmoidf_(g[1].w) * c4.w + sigmoidf_(g[0].w) * tanhf(g[2].w);

    float2 sc = make_float2(cv.x + cv.y + cv.z + cv.w,
                            cv.x*cv.x + cv.y*cv.y + cv.z*cv.z + cv.w*cv.w);
    float2 rc = block_sum2(sc, red_c);
    const float inv_h = 1.f / (float)HDIM;
    float mu_c = rc.x * inv_h;
    float rs_c = rsqrtf(rc.y * inv_h - mu_c * mu_c + 1e-5f);

    float4 wc = ((const float4*)ln_c_w)[tid], bc = ((const float4*)ln_c_b)[tid];
    float4 cy, hy;
    cy.x = (cv.x - mu_c) * rs_c * wc.x + bc.x;  hy.x = sigmoidf_(g[3].x) * tanhf(cy.x);
    cy.y = (cv.y - mu_c) * rs_c * wc.y + bc.y;  hy.y = sigmoidf_(g[3].y) * tanhf(cy.y);
    cy.z = (cv.z - mu_c) * rs_c * wc.z + bc.z;  hy.z = sigmoidf_(g[3].z) * tanhf(cy.z);
    cy.w = (cv.w - mu_c) * rs_c * wc.w + bc.w;  hy.w = sigmoidf_(g[3].w) * tanhf(cy.w);

    ((float4*)out)[(size_t)b * 256 + tid] = hy;
    ((float4*)out)[(size_t)BATCH * 256 + (size_t)b * 256 + tid] = cy;
}

// ---------------------------------------------------------------------------
extern "C" void kernel_launch(void* const* d_in, const int* in_sizes, int n_in,
                              void* d_out, int out_size)
{
    const float* input  = (const float*)d_in[0];
    const float* hx     = (const float*)d_in[1];
    const float* cx     = (const float*)d_in[2];
    const float* wih    = (const float*)d_in[3];
    const float* whh    = (const float*)d_in[4];
    const float* ln_i_w = (const float*)d_in[5];
    const float* ln_i_b = (const float*)d_in[6];
    const float* ln_h_w = (const float*)d_in[7];
    const float* ln_h_b = (const float*)d_in[8];
    const float* ln_c_w = (const float*)d_in[9];
    const float* ln_c_b = (const float*)d_in[10];
    float* out = (float*)d_out;

    cudaFuncSetAttribute(gemm_f16_kernel,
                         cudaFuncAttributeMaxDynamicSharedMemorySize, SMEM_TOTAL);

    __half *dA, *dH, *dWi, *dWh;
    cudaGetSymbolAddress((void**)&dA,  g_A);
    cudaGetSymbolAddress((void**)&dH,  g_H);
    cudaGetSymbolAddress((void**)&dWi, g_Wi);
    cudaGetSymbolAddress((void**)&dWh, g_Wh);

    cvt_fp16_kernel<<<dim3(296, 4), 256>>>(input, hx, wih, whh, dA, dH, dWi, dWh);

    dim3 grid(FH / BN, BATCH / BM, 2);
    gemm_f16_kernel<<<grid, 256, SMEM_TOTAL>>>(dA, dH, dWi, dWh);
    fuse_kernel<<<BATCH, 256>>>(cx, ln_i_w, ln_i_b, ln_h_w, ln_h_b, ln_c_w, ln_c_b, out);
}

// round 12
// speedup vs baseline: 2.6334x; 1.0005x over previous
#include <cuda_runtime.h>
#include <cuda_fp16.h>
#include <math.h>
#include <stdint.h>

#define BATCH 8192
#define KDIM  1024
#define HDIM  1024
#define FH    4096

// Scratch: fp16 gate pre-activations + fp16 operand copies.
__device__ __half g_ig[(size_t)BATCH * FH];
__device__ __half g_hg[(size_t)BATCH * FH];
__device__ __half g_A [(size_t)BATCH * KDIM];
__device__ __half g_H [(size_t)BATCH * KDIM];
__device__ __half g_Wi[(size_t)FH * KDIM];
__device__ __half g_Wh[(size_t)FH * KDIM];

// ---------------------------------------------------------------------------
// fp32 -> fp16 (RN) conversion, all 4 tensors in one launch.
// ---------------------------------------------------------------------------
__global__ void __launch_bounds__(256)
cvt_fp16_kernel(const float* __restrict__ s0, const float* __restrict__ s1,
                const float* __restrict__ s2, const float* __restrict__ s3,
                __half* __restrict__ d0, __half* __restrict__ d1,
                __half* __restrict__ d2, __half* __restrict__ d3)
{
    const float* src; __half* dst; int n4;
    switch (blockIdx.y) {
        case 0: src = s0; dst = d0; n4 = (BATCH * KDIM) / 4; break;
        case 1: src = s1; dst = d1; n4 = (BATCH * KDIM) / 4; break;
        case 2: src = s2; dst = d2; n4 = (FH * KDIM) / 4; break;
        default: src = s3; dst = d3; n4 = (FH * KDIM) / 4; break;
    }
    int i = blockIdx.x * blockDim.x + threadIdx.x;
    int stride = gridDim.x * blockDim.x;
    for (; i < n4; i += stride) {
        float4 v = ((const float4*)src)[i];
        __half2 lo = __floats2half2_rn(v.x, v.y);
        __half2 hi = __floats2half2_rn(v.z, v.w);
        uint2 p;
        p.x = *(uint32_t*)&lo;
        p.y = *(uint32_t*)&hi;
        ((uint2*)dst)[i] = p;
    }
}

// ---------------------------------------------------------------------------
// GEMM: out[m,n] = sum_k A[m,k] * W[n,k]  via mma.sync m16n8k16.f16 (fp32 acc)
// CTA tile 128x256, K-chunk 64, 3 stages, 8 warps (2x4), warp tile 64x64.
// At the measured legacy tensor-pipe MAC floor (~141 MACs/cyc/SMSP): frozen.
// ---------------------------------------------------------------------------
#define BM 128
#define BN 256
#define KC 64
#define NCHUNK (KDIM / KC)                 // 16
#define ROWB  144                          // 64 fp16 = 128B data + 16B pad
#define A_B   (BM * ROWB)                  // 18432
#define B_B   (BN * ROWB)                  // 36864
#define STAGE_BYTES (A_B + B_B)            // 55296
#define SMEM_TOTAL (3 * STAGE_BYTES)       // 165888
#define NTHREADS 256

__device__ __forceinline__ uint32_t smem_u32(const void* p) {
    uint32_t a;
    asm("{ .reg .u64 t; cvta.to.shared.u64 t, %1; cvt.u32.u64 %0, t; }" : "=r"(a) : "l"(p));
    return a;
}

__device__ __forceinline__ void cp16(uint32_t saddr, const void* g) {
    asm volatile("cp.async.cg.shared.global [%0], [%1], 16;" :: "r"(saddr), "l"(g));
}
#define CP_COMMIT() asm volatile("cp.async.commit_group;" ::: "memory")
#define CP_WAIT_1() asm volatile("cp.async.wait_group 1;" ::: "memory")

__device__ __forceinline__ void ldsm4(uint32_t& r0, uint32_t& r1, uint32_t& r2, uint32_t& r3,
                                      uint32_t addr) {
    asm volatile("ldmatrix.sync.aligned.m8n8.x4.shared.b16 {%0,%1,%2,%3}, [%4];"
                 : "=r"(r0), "=r"(r1), "=r"(r2), "=r"(r3) : "r"(addr));
}

__device__ __forceinline__ void mma_f16(float c[4], const uint32_t a[4], const uint32_t b[2]) {
    asm volatile(
        "mma.sync.aligned.m16n8k16.row.col.f32.f16.f16.f32 "
        "{%0,%1,%2,%3}, {%4,%5,%6,%7}, {%8,%9}, {%0,%1,%2,%3};"
        : "+f"(c[0]), "+f"(c[1]), "+f"(c[2]), "+f"(c[3])
        : "r"(a[0]), "r"(a[1]), "r"(a[2]), "r"(a[3]),
          "r"(b[0]), "r"(b[1]));
}

__global__ void __launch_bounds__(NTHREADS, 1)
gemm_f16_kernel(const __half* __restrict__ gA, const __half* __restrict__ gH,
                const __half* __restrict__ gWi, const __half* __restrict__ gWh)
{
    extern __shared__ char smem[];
    const uint32_t sbase = smem_u32(smem);

    const __half* A  = (blockIdx.z == 0) ? gA  : gH;
    const __half* W  = (blockIdx.z == 0) ? gWi : gWh;
    __half*      out = (blockIdx.z == 0) ? g_ig : g_hg;

    const int tid  = threadIdx.x;
    const int wid  = tid >> 5;
    const int lane = tid & 31;
    const int wm   = wid >> 2;
    const int wn   = wid & 3;
    const int m0   = blockIdx.y * BM;
    const int n0   = blockIdx.x * BN;

    const int ldrow = tid >> 3;
    const int ldc   = tid & 7;

    auto load_stage = [&](int st, int c) {
        const uint32_t sA = sbase + st * STAGE_BYTES;
        const uint32_t sB = sA + A_B;
        const int kt = c * KC;
        #pragma unroll
        for (int i = 0; i < 4; i++) {
            int row = ldrow + i * 32;
            cp16(sA + row * ROWB + ldc * 16,
                 &A[(size_t)(m0 + row) * KDIM + kt + ldc * 8]);
        }
        #pragma unroll
        for (int i = 0; i < 8; i++) {
            int row = ldrow + i * 32;
            cp16(sB + row * ROWB + ldc * 16,
                 &W[(size_t)(n0 + row) * KDIM + kt + ldc * 8]);
        }
    };

    const int lrow = lane & 15;
    const int lkof = (lane >> 4) * 16;
    uint32_t offA[4], offB[4];
    #pragma unroll
    for (int mt = 0; mt < 4; mt++)
        offA[mt] = (wm * 64 + mt * 16 + lrow) * ROWB + lkof;
    #pragma unroll
    for (int p = 0; p < 4; p++)
        offB[p] = (uint32_t)A_B + (wn * 64 + p * 16 + lrow) * ROWB + lkof;

    float acc[4][8][4];
    #pragma unroll
    for (int mt = 0; mt < 4; mt++)
        #pragma unroll
        for (int nt = 0; nt < 8; nt++)
            #pragma unroll
            for (int r = 0; r < 4; r++)
                acc[mt][nt][r] = 0.f;

    load_stage(0, 0); CP_COMMIT();
    load_stage(1, 1); CP_COMMIT();

    int st = 0;
    for (int c = 0; c < NCHUNK; c++) {
        CP_WAIT_1();
        __syncthreads();

        int st2 = st + 2; if (st2 >= 3) st2 -= 3;
        if (c + 2 < NCHUNK) load_stage(st2, c + 2);
        CP_COMMIT();

        const uint32_t sb = sbase + st * STAGE_BYTES;

        #pragma unroll
        for (int ks = 0; ks < 4; ks++) {
            const uint32_t kb = ks * 32;

            uint32_t af[4][4];
            #pragma unroll
            for (int mt = 0; mt < 4; mt++)
                ldsm4(af[mt][0], af[mt][1], af[mt][2], af[mt][3], sb + offA[mt] + kb);
            uint32_t bf[8][2];
            #pragma unroll
            for (int p = 0; p < 4; p++)
                ldsm4(bf[2*p][0], bf[2*p+1][0], bf[2*p][1], bf[2*p+1][1],
                      sb + offB[p] + kb);
            #pragma unroll
            for (int mt = 0; mt < 4; mt++)
                #pragma unroll
                for (int nt = 0; nt < 8; nt++)
                    mma_f16(acc[mt][nt], af[mt], bf[nt]);
        }

        if (++st >= 3) st -= 3;
    }

    // epilogue: fp16 stores
    #pragma unroll
    for (int mt = 0; mt < 4; mt++) {
        int row0 = m0 + wm * 64 + mt * 16 + (lane >> 2);
        #pragma unroll
        for (int nt = 0; nt < 8; nt++) {
            int col0 = n0 + wn * 64 + nt * 8 + 2 * (lane & 3);
            __half2 v0 = __floats2half2_rn(acc[mt][nt][0], acc[mt][nt][1]);
            __half2 v1 = __floats2half2_rn(acc[mt][nt][2], acc[mt][nt][3]);
            *(__half2*)&out[(size_t)row0 * FH + col0]       = v0;
            *(__half2*)&out[(size_t)(row0 + 8) * FH + col0] = v1;
        }
    }
}

// ---------------------------------------------------------------------------
// Fused LayerNorm + LSTM gates + cell LayerNorm. fp16 gates kept PACKED in
// registers (converted on use) to cut regs ~62 -> ~48 and raise occupancy.
// ---------------------------------------------------------------------------
__device__ __forceinline__ float sigmoidf_(float x) {
    return 1.f / (1.f + expf(-x));
}

__device__ __forceinline__ float4 unpack4(uint2 u) {
    __half2 h0 = *(__half2*)&u.x;
    __half2 h1 = *(__half2*)&u.y;
    float2 f0 = __half22float2(h0);
    float2 f1 = __half22float2(h1);
    return make_float4(f0.x, f0.y, f1.x, f1.y);
}

__device__ __forceinline__ float4 block_sum4(float4 v, float4* sh) {
    #pragma unroll
    for (int o = 16; o > 0; o >>= 1) {
        v.x += __shfl_down_sync(0xffffffffu, v.x, o);
        v.y += __shfl_down_sync(0xffffffffu, v.y, o);
        v.z += __shfl_down_sync(0xffffffffu, v.z, o);
        v.w += __shfl_down_sync(0xffffffffu, v.w, o);
    }
    int lane = threadIdx.x & 31, w = threadIdx.x >> 5;
    if (lane == 0) sh[w] = v;
    __syncthreads();
    if (w == 0) {
        float4 t = (lane < 8) ? sh[lane] : make_float4(0.f, 0.f, 0.f, 0.f);
        #pragma unroll
        for (int o = 4; o > 0; o >>= 1) {
            t.x += __shfl_down_sync(0xffffffffu, t.x, o);
            t.y += __shfl_down_sync(0xffffffffu, t.y, o);
            t.z += __shfl_down_sync(0xffffffffu, t.z, o);
            t.w += __shfl_down_sync(0xffffffffu, t.w, o);
        }
        if (lane == 0) sh[0] = t;
    }
    __syncthreads();
    return sh[0];
}

__device__ __forceinline__ float2 block_sum2(float2 v, float2* sh) {
    #pragma unroll
    for (int o = 16; o > 0; o >>= 1) {
        v.x += __shfl_down_sync(0xffffffffu, v.x, o);
        v.y += __shfl_down_sync(0xffffffffu, v.y, o);
    }
    int lane = threadIdx.x & 31, w = threadIdx.x >> 5;
    if (lane == 0) sh[w] = v;
    __syncthreads();
    if (w == 0) {
        float2 t = (lane < 8) ? sh[lane] : make_float2(0.f, 0.f);
        #pragma unroll
        for (int o = 4; o > 0; o >>= 1) {
            t.x += __shfl_down_sync(0xffffffffu, t.x, o);
            t.y += __shfl_down_sync(0xffffffffu, t.y, o);
        }
        if (lane == 0) sh[0] = t;
    }
    __syncthreads();
    return sh[0];
}

__global__ void __launch_bounds__(256, 5)
fuse_kernel(const float* __restrict__ cx,
            const float* __restrict__ ln_i_w, const float* __restrict__ ln_i_b,
            const float* __restrict__ ln_h_w, const float* __restrict__ ln_h_b,
            const float* __restrict__ ln_c_w, const float* __restrict__ ln_c_b,
            float* __restrict__ out)
{
    const int b   = blockIdx.x;
    const int tid = threadIdx.x;
    const uint2* ig2 = (const uint2*)(g_ig + (size_t)b * FH);
    const uint2* hg2 = (const uint2*)(g_hg + (size_t)b * FH);

    __shared__ float4 red4[8];
    __shared__ float2 red_c[8];

    // keep gates packed (fp16) — 16 regs instead of 32
    uint2 pi[4], ph[4];
    float4 s = make_float4(0.f, 0.f, 0.f, 0.f);
    #pragma unroll
    for (int p = 0; p < 4; p++) {
        int j = tid + p * 256;
        pi[p] = ig2[j];
        ph[p] = hg2[j];
        float4 a = unpack4(pi[p]);
        float4 c = unpack4(ph[p]);
        s.x += a.x + a.y + a.z + a.w;
        s.y += a.x*a.x + a.y*a.y + a.z*a.z + a.w*a.w;
        s.z += c.x + c.y + c.z + c.w;
        s.w += c.x*c.x + c.y*c.y + c.z*c.z + c.w*c.w;
    }
    float4 r = block_sum4(s, red4);

    const float inv_fh = 1.f / (float)FH;
    float mu_i = r.x * inv_fh;
    float rs_i = rsqrtf(r.y * inv_fh - mu_i * mu_i + 1e-5f);
    float mu_h = r.z * inv_fh;
    float rs_h = rsqrtf(r.w * inv_fh - mu_h * mu_h + 1e-5f);

    float4 g[4];
    #pragma unroll
    for (int p = 0; p < 4; p++) {
        int j = tid + p * 256;
        float4 wi = ((const float4*)ln_i_w)[j], bi = ((const float4*)ln_i_b)[j];
        float4 wh = ((const float4*)ln_h_w)[j], bh = ((const float4*)ln_h_b)[j];
        float4 a = unpack4(pi[p]);
        float4 c = unpack4(ph[p]);
        g[p].x = (a.x - mu_i) * rs_i * wi.x + bi.x + (c.x - mu_h) * rs_h * wh.x + bh.x;
        g[p].y = (a.y - mu_i) * rs_i * wi.y + bi.y + (c.y - mu_h) * rs_h * wh.y + bh.y;
        g[p].z = (a.z - mu_i) * rs_i * wi.z + bi.z + (c.z - mu_h) * rs_h * wh.z + bh.z;
        g[p].w = (a.w - mu_i) * rs_i * wi.w + bi.w + (c.w - mu_h) * rs_h * wh.w + bh.w;
    }

    float4 c4 = ((const float4*)cx)[b * 256 + tid];

    float4 cv;
    cv.x = sigmoidf_(g[1].x) * c4.x + sigmoidf_(g[0].x) * tanhf(g[2].x);
    cv.y = sigmoidf_(g[1].y) * c4.y + sigmoidf_(g[0].y) * tanhf(g[2].y);
    cv.z = sigmoidf_(g[1].z) * c4.z + sigmoidf_(g[0].z) * tanhf(g[2].z);
    cv.w = sigmoidf_(g[1].w) * c4.w + sigmoidf_(g[0].w) * tanhf(g[2].w);

    float2 sc = make_float2(cv.x + cv.y + cv.z + cv.w,
                            cv.x*cv.x + cv.y*cv.y + cv.z*cv.z + cv.w*cv.w);
    float2 rc = block_sum2(sc, red_c);
    const float inv_h = 1.f / (float)HDIM;
    float mu_c = rc.x * inv_h;
    float rs_c = rsqrtf(rc.y * inv_h - mu_c * mu_c + 1e-5f);

    float4 wc = ((const float4*)ln_c_w)[tid], bc = ((const float4*)ln_c_b)[tid];
    float4 cy, hy;
    cy.x = (cv.x - mu_c) * rs_c * wc.x + bc.x;  hy.x = sigmoidf_(g[3].x) * tanhf(cy.x);
    cy.y = (cv.y - mu_c) * rs_c * wc.y + bc.y;  hy.y = sigmoidf_(g[3].y) * tanhf(cy.y);
    cy.z = (cv.z - mu_c) * rs_c * wc.z + bc.z;  hy.z = sigmoidf_(g[3].z) * tanhf(cy.z);
    cy.w = (cv.w - mu_c) * rs_c * wc.w + bc.w;  hy.w = sigmoidf_(g[3].w) * tanhf(cy.w);

    ((float4*)out)[(size_t)b * 256 + tid] = hy;
    ((float4*)out)[(size_t)BATCH * 256 + (size_t)b * 256 + tid] = cy;
}

// ---------------------------------------------------------------------------
extern "C" void kernel_launch(void* const* d_in, const int* in_sizes, int n_in,
                              void* d_out, int out_size)
{
    const float* input  = (const float*)d_in[0];
    const float* hx     = (const float*)d_in[1];
    const float* cx     = (const float*)d_in[2];
    const float* wih    = (const float*)d_in[3];
    const float* whh    = (const float*)d_in[4];
    const float* ln_i_w = (const float*)d_in[5];
    const float* ln_i_b = (const float*)d_in[6];
    const float* ln_h_w = (const float*)d_in[7];
    const float* ln_h_b = (const float*)d_in[8];
    const float* ln_c_w = (const float*)d_in[9];
    const float* ln_c_b = (const float*)d_in[10];
    float* out = (float*)d_out;

    cudaFuncSetAttribute(gemm_f16_kernel,
                         cudaFuncAttributeMaxDynamicSharedMemorySize, SMEM_TOTAL);

    __half *dA, *dH, *dWi, *dWh;
    cudaGetSymbolAddress((void**)&dA,  g_A);
    cudaGetSymbolAddress((void**)&dH,  g_H);
    cudaGetSymbolAddress((void**)&dWi, g_Wi);
    cudaGetSymbolAddress((void**)&dWh, g_Wh);

    cvt_fp16_kernel<<<dim3(296, 4), 256>>>(input, hx, wih, whh, dA, dH, dWi, dWh);

    dim3 grid(FH / BN, BATCH / BM, 2);
    gemm_f16_kernel<<<grid, 256, SMEM_TOTAL>>>(dA, dH, dWi, dWh);
    fuse_kernel<<<BATCH, 256>>>(cx, ln_i_w, ln_i_b, ln_h_w, ln_h_b, ln_c_w, ln_c_b, out);
}